// round 3
// baseline (speedup 1.0000x reference)
#include <cuda_runtime.h>
#include <cuda_bf16.h>

#define N_NODES 50000
#define N_EDGES 800000
#define F 64
#define G 512
#define OUTD 32

// Scratch (device globals — no allocations allowed). 16B-aligned for red.v4.
__device__ __align__(16) float g_h[N_NODES * F];    // X @ W
__device__ __align__(16) float g_agg[N_NODES * F];  // neighbor aggregation
__device__ __align__(16) float g_hr[N_NODES * F];   // relu'd layer output
__device__ float g_inv[N_NODES];                    // 1/sqrt(deg+1)
__device__ int   g_deg[N_NODES];
__device__ __align__(16) float g_psum[G * F];
__device__ int   g_pcnt[G];

// ---------------- zero kernels ----------------
__global__ void k_zero_deg_pool(int* deg, float* psum, int* pcnt) {
    int i = blockIdx.x * blockDim.x + threadIdx.x;
    if (i < N_NODES) deg[i] = 0;
    if (i < G * F)   psum[i] = 0.0f;
    if (i < G)       pcnt[i] = 0;
}

__global__ void k_zero_agg(float4* agg4) {
    int i = blockIdx.x * blockDim.x + threadIdx.x;
    if (i < N_NODES * F / 4)
        agg4[i] = make_float4(0.f, 0.f, 0.f, 0.f);
}

// ---------------- degree / norm ----------------
__global__ void k_deg(const int* __restrict__ dst, int* deg) {
    int e = blockIdx.x * blockDim.x + threadIdx.x;
    if (e < N_EDGES) atomicAdd(&deg[dst[e]], 1);
}

__global__ void k_inv(const int* __restrict__ deg, float* inv) {
    int i = blockIdx.x * blockDim.x + threadIdx.x;
    if (i < N_NODES) inv[i] = rsqrtf((float)deg[i] + 1.0f);
}

// ---------------- GEMM: Y[N,64] = X[N,64] @ W[64,64] ----------------
__global__ void k_gemm(const float* __restrict__ X, const float* __restrict__ Wm,
                       float* __restrict__ Y, int nrows) {
    __shared__ float Ws[F * F];
    __shared__ float Xs[32 * F];
    int t = threadIdx.x;
    for (int i = t; i < F * F; i += 256) Ws[i] = Wm[i];
    int rowbase = blockIdx.x * 32;
    for (int i = t; i < 32 * F; i += 256) {
        int r = rowbase + i / F;
        Xs[i] = (r < nrows) ? X[r * F + (i % F)] : 0.0f;
    }
    __syncthreads();

    int col4 = (t & 15) * 4;
    int r0   = (t >> 4) * 2;
    float4 acc0 = make_float4(0.f, 0.f, 0.f, 0.f);
    float4 acc1 = make_float4(0.f, 0.f, 0.f, 0.f);
#pragma unroll
    for (int k = 0; k < F; k++) {
        float4 w = *reinterpret_cast<const float4*>(&Ws[k * F + col4]);
        float x0 = Xs[r0 * F + k];
        float x1 = Xs[(r0 + 1) * F + k];
        acc0.x += x0 * w.x; acc0.y += x0 * w.y; acc0.z += x0 * w.z; acc0.w += x0 * w.w;
        acc1.x += x1 * w.x; acc1.y += x1 * w.y; acc1.z += x1 * w.z; acc1.w += x1 * w.w;
    }
    int gr0 = rowbase + r0;
    if (gr0 < nrows)     *reinterpret_cast<float4*>(&Y[gr0 * F + col4])       = acc0;
    if (gr0 + 1 < nrows) *reinterpret_cast<float4*>(&Y[(gr0 + 1) * F + col4]) = acc1;
}

// ---------------- edge scatter: agg[dst] += h[src] * norm ----------------
// thread = (edge, feature quad). 16 lanes cover one edge's 64 features.
__global__ void k_scatter(const int* __restrict__ src,
                          const int* __restrict__ dst,
                          const float* __restrict__ inv,
                          const float* __restrict__ h,
                          float* __restrict__ agg) {
    long long t = (long long)blockIdx.x * blockDim.x + threadIdx.x;
    int e = (int)(t >> 4);
    if (e >= N_EDGES) return;
    int q = ((int)t & 15) * 4;
    int s = src[e];
    int d = dst[e];
    float nrm = inv[s] * inv[d];
    float4 v = *reinterpret_cast<const float4*>(&h[s * F + q]);
    float* p = &agg[d * F + q];
    asm volatile("red.global.add.v4.f32 [%0], {%1, %2, %3, %4};"
                 :: "l"(p), "f"(v.x * nrm), "f"(v.y * nrm),
                    "f"(v.z * nrm), "f"(v.w * nrm)
                 : "memory");
}

// ---------------- self-loop term + bias + relu ----------------
__global__ void k_self_relu(const float* __restrict__ b,
                            const float* __restrict__ inv,
                            const float* __restrict__ h,
                            const float* __restrict__ agg,
                            float* __restrict__ hr) {
    int t = blockIdx.x * blockDim.x + threadIdx.x;
    int i = t >> 4;
    if (i >= N_NODES) return;
    int q = (t & 15) * 4;
    float iv = inv[i];
    float s = iv * iv;
    float4 hv = *reinterpret_cast<const float4*>(&h[i * F + q]);
    float4 a  = *reinterpret_cast<const float4*>(&agg[i * F + q]);
    float4 o;
    o.x = fmaxf(a.x + hv.x * s + b[q + 0], 0.f);
    o.y = fmaxf(a.y + hv.y * s + b[q + 1], 0.f);
    o.z = fmaxf(a.z + hv.z * s + b[q + 2], 0.f);
    o.w = fmaxf(a.w + hv.w * s + b[q + 3], 0.f);
    *reinterpret_cast<float4*>(&hr[i * F + q]) = o;
}

// ---------------- global mean pool (accumulate) ----------------
__global__ void k_pool(const int* __restrict__ batch,
                       const float* __restrict__ hr,
                       float* __restrict__ psum, int* __restrict__ pcnt) {
    int t = blockIdx.x * blockDim.x + threadIdx.x;
    int i = t >> 4;
    if (i >= N_NODES) return;
    int q = (t & 15) * 4;
    int g = batch[i];
    float4 v = *reinterpret_cast<const float4*>(&hr[i * F + q]);
    float* p = &psum[g * F + q];
    asm volatile("red.global.add.v4.f32 [%0], {%1, %2, %3, %4};"
                 :: "l"(p), "f"(v.x), "f"(v.y), "f"(v.z), "f"(v.w)
                 : "memory");
    if (q == 0) atomicAdd(&pcnt[g], 1);
}

// ---------------- final FC: out[G,32] = (psum/cnt) @ fcW + fcb ----------------
__global__ void k_fc(const float* __restrict__ fcW, const float* __restrict__ fcb,
                     const float* __restrict__ psum, const int* __restrict__ pcnt,
                     float* __restrict__ out) {
    int t = blockIdx.x * blockDim.x + threadIdx.x;
    if (t >= G * OUTD) return;
    int g = t / OUTD;
    int o = t % OUTD;
    float cnt = fmaxf((float)pcnt[g], 1.0f);
    float inv = 1.0f / cnt;
    float acc = fcb[o];
#pragma unroll
    for (int k = 0; k < F; k++)
        acc += psum[g * F + k] * inv * fcW[k * OUTD + o];
    out[t] = acc;
}

extern "C" void kernel_launch(void* const* d_in, const int* in_sizes, int n_in,
                              void* d_out, int out_size) {
    const float* x   = (const float*)d_in[0];
    const float* W1  = (const float*)d_in[1];
    const float* b1  = (const float*)d_in[2];
    const float* W2  = (const float*)d_in[3];
    const float* b2  = (const float*)d_in[4];
    const float* fcW = (const float*)d_in[5];
    const float* fcb = (const float*)d_in[6];
    const int* edge_index = (const int*)d_in[7];  // int32! (JAX x64 disabled)
    const int* batch      = (const int*)d_in[8];
    float* out = (float*)d_out;

    const int* src = edge_index;
    const int* dst = edge_index + N_EDGES;

    // Resolve device addresses of __device__ scratch (host symbol != device ptr!)
    float *p_h, *p_agg, *p_hr, *p_inv, *p_psum;
    int *p_deg, *p_pcnt;
    cudaGetSymbolAddress((void**)&p_h,    g_h);
    cudaGetSymbolAddress((void**)&p_agg,  g_agg);
    cudaGetSymbolAddress((void**)&p_hr,   g_hr);
    cudaGetSymbolAddress((void**)&p_inv,  g_inv);
    cudaGetSymbolAddress((void**)&p_psum, g_psum);
    cudaGetSymbolAddress((void**)&p_deg,  g_deg);
    cudaGetSymbolAddress((void**)&p_pcnt, g_pcnt);

    const int NF4     = N_NODES * F / 4;          // 800000
    const int gridNF4 = (NF4 + 255) / 256;        // 3125
    const int gridE   = (N_EDGES + 255) / 256;    // 3125
    const int gridN   = (N_NODES + 255) / 256;    // 196
    const int gridEdgeQuad = (N_EDGES * 16 + 255) / 256;  // 50000
    const int gridNodeQuad = (N_NODES * 16 + 255) / 256;  // 3125
    const int gridGemm = (N_NODES + 31) / 32;     // 1563

    // init
    k_zero_deg_pool<<<gridNF4, 256>>>(p_deg, p_psum, p_pcnt);
    k_zero_agg<<<gridNF4, 256>>>((float4*)p_agg);
    k_deg<<<gridE, 256>>>(dst, p_deg);
    k_inv<<<gridN, 256>>>(p_deg, p_inv);

    // layer 1
    k_gemm<<<gridGemm, 256>>>(x, W1, p_h, N_NODES);
    k_scatter<<<gridEdgeQuad, 256>>>(src, dst, p_inv, p_h, p_agg);
    k_self_relu<<<gridNodeQuad, 256>>>(b1, p_inv, p_h, p_agg, p_hr);

    // layer 2
    k_zero_agg<<<gridNF4, 256>>>((float4*)p_agg);
    k_gemm<<<gridGemm, 256>>>(p_hr, W2, p_h, N_NODES);
    k_scatter<<<gridEdgeQuad, 256>>>(src, dst, p_inv, p_h, p_agg);
    k_self_relu<<<gridNodeQuad, 256>>>(b2, p_inv, p_h, p_agg, p_hr);

    // pool + fc
    k_pool<<<gridNodeQuad, 256>>>(batch, p_hr, p_psum, p_pcnt);
    k_fc<<<(G * OUTD + 255) / 256, 256>>>(fcW, fcb, p_psum, p_pcnt, out);
}

// round 4
// speedup vs baseline: 1.0750x; 1.0750x over previous
#include <cuda_runtime.h>
#include <cuda_bf16.h>

#define N_NODES 50000
#define N_EDGES 800000
#define F 64
#define G 512
#define OUTD 32

// Scratch (device globals). 16B-aligned for red.v4 / float4.
__device__ __align__(16) float g_hs[N_NODES * F];   // (X @ W) * inv[row]
__device__ __align__(16) float g_agg[N_NODES * F];  // neighbor aggregation (of hs)
__device__ __align__(16) float g_hr[N_NODES * F];   // relu'd layer-1 output
__device__ float g_inv[N_NODES];                    // 1/sqrt(deg+1)
__device__ int   g_deg[N_NODES];
__device__ __align__(16) float g_psum[G * F];
__device__ int   g_pcnt[G];

// ---------------- init: zero deg/psum/pcnt ----------------
__global__ void k_init(int* deg, float* psum, int* pcnt) {
    int i = blockIdx.x * blockDim.x + threadIdx.x;
    if (i < N_NODES) deg[i] = 0;
    if (i < G * F)   psum[i] = 0.0f;
    if (i < G)       pcnt[i] = 0;
}

// ---------------- degree ----------------
__global__ void k_deg(const int* __restrict__ dst, int* deg) {
    int e = blockIdx.x * blockDim.x + threadIdx.x;
    if (e < N_EDGES) atomicAdd(&deg[dst[e]], 1);
}

// ---------------- inv norm + per-graph node counts ----------------
__global__ void k_inv(const int* __restrict__ deg, float* inv,
                      const int* __restrict__ batch, int* pcnt) {
    int i = blockIdx.x * blockDim.x + threadIdx.x;
    if (i < N_NODES) {
        inv[i] = rsqrtf((float)deg[i] + 1.0f);
        atomicAdd(&pcnt[batch[i]], 1);
    }
}

// ---------------- GEMM: hs[N,64] = (X[N,64] @ W[64,64]) * inv[row]; agg=0 ----
// 256 threads/block, 32 rows/block; each thread computes 2 rows x 4 cols.
__global__ void k_gemm(const float* __restrict__ X, const float* __restrict__ Wm,
                       const float* __restrict__ inv,
                       float* __restrict__ hs, float* __restrict__ agg) {
    __shared__ float Ws[F * F];
    __shared__ float Xs[32 * F];
    int t = threadIdx.x;
    for (int i = t; i < F * F; i += 256) Ws[i] = Wm[i];
    int rowbase = blockIdx.x * 32;
    for (int i = t; i < 32 * F; i += 256) {
        int r = rowbase + (i >> 6);
        Xs[i] = (r < N_NODES) ? X[r * F + (i & 63)] : 0.0f;
    }
    __syncthreads();

    int col4 = (t & 15) * 4;
    int r0   = (t >> 4) * 2;
    float4 acc0 = make_float4(0.f, 0.f, 0.f, 0.f);
    float4 acc1 = make_float4(0.f, 0.f, 0.f, 0.f);
#pragma unroll
    for (int k = 0; k < F; k++) {
        float4 w = *reinterpret_cast<const float4*>(&Ws[k * F + col4]);
        float x0 = Xs[r0 * F + k];
        float x1 = Xs[(r0 + 1) * F + k];
        acc0.x += x0 * w.x; acc0.y += x0 * w.y; acc0.z += x0 * w.z; acc0.w += x0 * w.w;
        acc1.x += x1 * w.x; acc1.y += x1 * w.y; acc1.z += x1 * w.z; acc1.w += x1 * w.w;
    }
    int gr0 = rowbase + r0;
    float4 zero = make_float4(0.f, 0.f, 0.f, 0.f);
    if (gr0 < N_NODES) {
        float s = inv[gr0];
        acc0.x *= s; acc0.y *= s; acc0.z *= s; acc0.w *= s;
        *reinterpret_cast<float4*>(&hs[gr0 * F + col4])  = acc0;
        *reinterpret_cast<float4*>(&agg[gr0 * F + col4]) = zero;
    }
    if (gr0 + 1 < N_NODES) {
        float s = inv[gr0 + 1];
        acc1.x *= s; acc1.y *= s; acc1.z *= s; acc1.w *= s;
        *reinterpret_cast<float4*>(&hs[(gr0 + 1) * F + col4])  = acc1;
        *reinterpret_cast<float4*>(&agg[(gr0 + 1) * F + col4]) = zero;
    }
}

// ---------------- edge scatter: agg[dst] += hs[src] ----------------
// thread = (edge, feature quad). 16 lanes cover one edge's 64 features.
__global__ void k_scatter(const int* __restrict__ src,
                          const int* __restrict__ dst,
                          const float* __restrict__ hs,
                          float* __restrict__ agg) {
    unsigned t = blockIdx.x * 256u + threadIdx.x;
    unsigned e = t >> 4;
    if (e >= N_EDGES) return;
    int q = (t & 15) * 4;
    int s = src[e];
    int d = dst[e];
    float4 v = *reinterpret_cast<const float4*>(&hs[s * F + q]);
    float* p = &agg[d * F + q];
    asm volatile("red.global.add.v4.f32 [%0], {%1, %2, %3, %4};"
                 :: "l"(p), "f"(v.x), "f"(v.y), "f"(v.z), "f"(v.w)
                 : "memory");
}

// ---------------- layer-1 epilogue: hr = relu(inv*(agg+hs) + b) ----------------
__global__ void k_self_relu(const float* __restrict__ b,
                            const float* __restrict__ inv,
                            const float* __restrict__ hs,
                            const float* __restrict__ agg,
                            float* __restrict__ hr) {
    int t = blockIdx.x * blockDim.x + threadIdx.x;
    int i = t >> 4;
    if (i >= N_NODES) return;
    int q = (t & 15) * 4;
    float iv = inv[i];
    float4 hv = *reinterpret_cast<const float4*>(&hs[i * F + q]);
    float4 a  = *reinterpret_cast<const float4*>(&agg[i * F + q]);
    float4 o;
    o.x = fmaxf((a.x + hv.x) * iv + b[q + 0], 0.f);
    o.y = fmaxf((a.y + hv.y) * iv + b[q + 1], 0.f);
    o.z = fmaxf((a.z + hv.z) * iv + b[q + 2], 0.f);
    o.w = fmaxf((a.w + hv.w) * iv + b[q + 3], 0.f);
    *reinterpret_cast<float4*>(&hr[i * F + q]) = o;
}

// ---------------- layer-2 epilogue fused with mean-pool accumulate ----------
__global__ void k_self_relu_pool(const float* __restrict__ b,
                                 const float* __restrict__ inv,
                                 const float* __restrict__ hs,
                                 const float* __restrict__ agg,
                                 const int* __restrict__ batch,
                                 float* __restrict__ psum) {
    int t = blockIdx.x * blockDim.x + threadIdx.x;
    int i = t >> 4;
    if (i >= N_NODES) return;
    int q = (t & 15) * 4;
    float iv = inv[i];
    float4 hv = *reinterpret_cast<const float4*>(&hs[i * F + q]);
    float4 a  = *reinterpret_cast<const float4*>(&agg[i * F + q]);
    float4 o;
    o.x = fmaxf((a.x + hv.x) * iv + b[q + 0], 0.f);
    o.y = fmaxf((a.y + hv.y) * iv + b[q + 1], 0.f);
    o.z = fmaxf((a.z + hv.z) * iv + b[q + 2], 0.f);
    o.w = fmaxf((a.w + hv.w) * iv + b[q + 3], 0.f);
    int g = batch[i];
    float* p = &psum[g * F + q];
    asm volatile("red.global.add.v4.f32 [%0], {%1, %2, %3, %4};"
                 :: "l"(p), "f"(o.x), "f"(o.y), "f"(o.z), "f"(o.w)
                 : "memory");
}

// ---------------- final FC: out[G,32] = (psum/cnt) @ fcW + fcb ----------------
__global__ void k_fc(const float* __restrict__ fcW, const float* __restrict__ fcb,
                     const float* __restrict__ psum, const int* __restrict__ pcnt,
                     float* __restrict__ out) {
    int t = blockIdx.x * blockDim.x + threadIdx.x;
    if (t >= G * OUTD) return;
    int g = t / OUTD;
    int o = t % OUTD;
    float cnt = fmaxf((float)pcnt[g], 1.0f);
    float invc = 1.0f / cnt;
    float acc = fcb[o];
#pragma unroll
    for (int k = 0; k < F; k++)
        acc += psum[g * F + k] * invc * fcW[k * OUTD + o];
    out[t] = acc;
}

extern "C" void kernel_launch(void* const* d_in, const int* in_sizes, int n_in,
                              void* d_out, int out_size) {
    const float* x   = (const float*)d_in[0];
    const float* W1  = (const float*)d_in[1];
    const float* b1  = (const float*)d_in[2];
    const float* W2  = (const float*)d_in[3];
    const float* b2  = (const float*)d_in[4];
    const float* fcW = (const float*)d_in[5];
    const float* fcb = (const float*)d_in[6];
    const int* edge_index = (const int*)d_in[7];  // int32 (JAX x64 disabled)
    const int* batch      = (const int*)d_in[8];
    float* out = (float*)d_out;

    const int* src = edge_index;
    const int* dst = edge_index + N_EDGES;

    float *p_hs, *p_agg, *p_hr, *p_inv, *p_psum;
    int *p_deg, *p_pcnt;
    cudaGetSymbolAddress((void**)&p_hs,   g_hs);
    cudaGetSymbolAddress((void**)&p_agg,  g_agg);
    cudaGetSymbolAddress((void**)&p_hr,   g_hr);
    cudaGetSymbolAddress((void**)&p_inv,  g_inv);
    cudaGetSymbolAddress((void**)&p_psum, g_psum);
    cudaGetSymbolAddress((void**)&p_deg,  g_deg);
    cudaGetSymbolAddress((void**)&p_pcnt, g_pcnt);

    const int gridE   = (N_EDGES + 255) / 256;            // 3125
    const int gridN   = (N_NODES + 255) / 256;            // 196
    const int gridEdgeQuad = (N_EDGES * 16 + 255) / 256;  // 50000
    const int gridNodeQuad = (N_NODES * 16 + 255) / 256;  // 3125
    const int gridGemm = (N_NODES + 31) / 32;             // 1563

    // prep
    k_init<<<gridN, 256>>>(p_deg, p_psum, p_pcnt);
    k_deg<<<gridE, 256>>>(dst, p_deg);
    k_inv<<<gridN, 256>>>(p_deg, p_inv, batch, p_pcnt);

    // layer 1
    k_gemm<<<gridGemm, 256>>>(x, W1, p_inv, p_hs, p_agg);
    k_scatter<<<gridEdgeQuad, 256>>>(src, dst, p_hs, p_agg);
    k_self_relu<<<gridNodeQuad, 256>>>(b1, p_inv, p_hs, p_agg, p_hr);

    // layer 2
    k_gemm<<<gridGemm, 256>>>(p_hr, W2, p_inv, p_hs, p_agg);
    k_scatter<<<gridEdgeQuad, 256>>>(src, dst, p_hs, p_agg);
    k_self_relu_pool<<<gridNodeQuad, 256>>>(b2, p_inv, p_hs, p_agg, batch, p_psum);

    // fc
    k_fc<<<(G * OUTD + 255) / 256, 256>>>(fcW, fcb, p_psum, p_pcnt, out);
}